// round 1
// baseline (speedup 1.0000x reference)
#include <cuda_runtime.h>
#include <math.h>

// ---------------- problem constants ----------------
#define TT   8192      // tokens (B*S)
#define DD   2048      // model dim
#define HH   1368      // hidden dim
#define EE   8         // experts
#define TK   16384     // T * K assignments

// ---------------- static device scratch ----------------
__device__ __align__(16) float g_bufA[(size_t)TK * HH];   // 89.7 MB
__device__ __align__(16) float g_bufB[(size_t)TK * HH];   // 89.7 MB
__device__ __align__(16) float g_yslot[(size_t)TK * DD];  // 134 MB
__device__ int   g_assign_tok[TK];
__device__ float g_assign_gate[TK];
__device__ int   g_tok_pos[TK];       // token t -> assignment slots 2t, 2t+1
__device__ int2  g_top_e[TT];
__device__ float2 g_top_p[TT];
__device__ int   g_cnt1[EE];
__device__ int   g_cntA[EE];
__device__ int   g_cursor[EE];
__device__ int   g_offsets[EE + 1];
__device__ float g_psum[EE];

// ---------------- packed f32x2 helpers ----------------
__device__ __forceinline__ unsigned long long pk2(float lo, float hi) {
    unsigned long long r;
    asm("mov.b64 %0, {%1, %2};" : "=l"(r) : "f"(lo), "f"(hi));
    return r;
}
__device__ __forceinline__ void upk2(unsigned long long v, float& lo, float& hi) {
    asm("mov.b64 {%0, %1}, %2;" : "=f"(lo), "=f"(hi) : "l"(v));
}
#define FMA2(acc, a, b) \
    asm("fma.rn.f32x2 %0, %1, %2, %0;" : "+l"(acc) : "l"(a), "l"(b))

// ---------------- init ----------------
__global__ void init_kernel() {
    int i = threadIdx.x;
    if (i < EE) { g_cnt1[i] = 0; g_cntA[i] = 0; g_psum[i] = 0.f; g_cursor[i] = 0; }
}

// ---------------- router: one warp per token ----------------
__global__ void router_kernel(const float* __restrict__ x,
                              const float* __restrict__ rw) {
    __shared__ float s_psum[EE];
    __shared__ int s_cnt1[EE], s_cntA[EE];
    int tid = threadIdx.x;
    if (tid < EE) { s_psum[tid] = 0.f; s_cnt1[tid] = 0; s_cntA[tid] = 0; }
    __syncthreads();

    int warp = tid >> 5, lane = tid & 31;
    int t = blockIdx.x * 8 + warp;

    float acc[EE];
#pragma unroll
    for (int e = 0; e < EE; e++) acc[e] = 0.f;

    const float4* xr = reinterpret_cast<const float4*>(x + (long long)t * DD);
    for (int d4 = lane; d4 < DD / 4; d4 += 32) {
        float4 xv = xr[d4];
#pragma unroll
        for (int e = 0; e < EE; e++) {
            float4 wv = reinterpret_cast<const float4*>(rw + (long long)e * DD)[d4];
            acc[e] += xv.x * wv.x + xv.y * wv.y + xv.z * wv.z + xv.w * wv.w;
        }
    }
#pragma unroll
    for (int e = 0; e < EE; e++)
        for (int o = 16; o; o >>= 1)
            acc[e] += __shfl_xor_sync(0xffffffffu, acc[e], o);

    if (lane == 0) {
        float mx = acc[0];
#pragma unroll
        for (int e = 1; e < EE; e++) mx = fmaxf(mx, acc[e]);
        float p[EE], s = 0.f;
#pragma unroll
        for (int e = 0; e < EE; e++) { p[e] = expf(acc[e] - mx); s += p[e]; }
        float inv = 1.f / s;
        // top-2 on logits, lowest index wins ties (jax top_k convention)
        int e0 = 0;
#pragma unroll
        for (int e = 1; e < EE; e++) if (acc[e] > acc[e0]) e0 = e;
        int e1 = (e0 == 0) ? 1 : 0;
#pragma unroll
        for (int e = 0; e < EE; e++) if (e != e0 && acc[e] > acc[e1]) e1 = e;

        g_top_e[t] = make_int2(e0, e1);
        g_top_p[t] = make_float2(p[e0] * inv, p[e1] * inv);
        atomicAdd(&s_cnt1[e0], 1);
        atomicAdd(&s_cntA[e0], 1);
        atomicAdd(&s_cntA[e1], 1);
#pragma unroll
        for (int e = 0; e < EE; e++) atomicAdd(&s_psum[e], p[e] * inv);
    }
    __syncthreads();
    if (tid < EE) {
        atomicAdd(&g_psum[tid], s_psum[tid]);
        atomicAdd(&g_cnt1[tid], s_cnt1[tid]);
        atomicAdd(&g_cntA[tid], s_cntA[tid]);
    }
}

// ---------------- scan: offsets + aux loss ----------------
__global__ void scan_kernel(float* __restrict__ aux_out) {
    if (threadIdx.x == 0) {
        int off = 0;
        for (int e = 0; e < EE; e++) { g_offsets[e] = off; off += g_cntA[e]; }
        g_offsets[EE] = off;
        float aux = 0.f;
        const float invT = 1.0f / (float)TT;
        for (int e = 0; e < EE; e++)
            aux += ((float)g_cnt1[e] * invT) * (g_psum[e] * invT);
        aux_out[0] = 0.01f * (float)EE * aux;
    }
}

// ---------------- build assignment lists ----------------
__global__ void build_kernel() {
    int t = blockIdx.x * blockDim.x + threadIdx.x;
    if (t >= TT) return;
    int2 e = g_top_e[t];
    float2 p = g_top_p[t];
    int pos0 = g_offsets[e.x] + atomicAdd(&g_cursor[e.x], 1);
    g_assign_tok[pos0] = t; g_assign_gate[pos0] = p.x; g_tok_pos[2 * t] = pos0;
    int pos1 = g_offsets[e.y] + atomicAdd(&g_cursor[e.y], 1);
    g_assign_tok[pos1] = t; g_assign_gate[pos1] = p.y; g_tok_pos[2 * t + 1] = pos1;
}

// ---------------- tiled NT GEMM (C[m,n] = sum_k A[g(m),k] * W[e][n,k]) ------
#define BM 128
#define BN 128
#define BK 16
#define SROW (BM + 4)

__global__ __launch_bounds__(256, 2)
void gemm_nt(const float* __restrict__ A,
             const float* __restrict__ W,
             float* __restrict__ C,
             const int*   __restrict__ gather,
             const float* __restrict__ gate,
             const int*   __restrict__ segoff,
             int Mtotal, int N, int K, int ldc, long long wstride) {
    __shared__ __align__(16) float As[BK][SROW];
    __shared__ __align__(16) float Bs[BK][SROW];

    int e = blockIdx.z;
    int m_begin = 0, m_end = Mtotal;
    if (segoff) { m_begin = segoff[e]; m_end = segoff[e + 1]; }
    const float* Wp = W + (long long)e * wstride;

    int row0 = m_begin + blockIdx.x * BM;
    if (row0 >= m_end) return;
    int col0 = blockIdx.y * BN;

    int tid = threadIdx.x;
    int tx = tid & 15;
    int ty = tid >> 4;

    unsigned long long acc[8][4];
#pragma unroll
    for (int i = 0; i < 8; i++)
#pragma unroll
        for (int j = 0; j < 4; j++) acc[i][j] = 0ULL;

    int ldrow = tid >> 2;          // 0..63
    int ldk   = (tid & 3) * 4;     // 0,4,8,12

    for (int k0 = 0; k0 < K; k0 += BK) {
#pragma unroll
        for (int rr = 0; rr < 2; rr++) {
            int mloc = ldrow + rr * 64;
            int m = row0 + mloc;
            float4 v = make_float4(0.f, 0.f, 0.f, 0.f);
            if (m < m_end && (k0 + ldk) < K) {
                int ar = gather ? gather[m] : m;
                v = *reinterpret_cast<const float4*>(A + (long long)ar * K + k0 + ldk);
            }
            As[ldk + 0][mloc] = v.x; As[ldk + 1][mloc] = v.y;
            As[ldk + 2][mloc] = v.z; As[ldk + 3][mloc] = v.w;
        }
#pragma unroll
        for (int rr = 0; rr < 2; rr++) {
            int nloc = ldrow + rr * 64;
            int n = col0 + nloc;
            float4 v = make_float4(0.f, 0.f, 0.f, 0.f);
            if (n < N && (k0 + ldk) < K) {
                v = *reinterpret_cast<const float4*>(Wp + (long long)n * K + k0 + ldk);
            }
            Bs[ldk + 0][nloc] = v.x; Bs[ldk + 1][nloc] = v.y;
            Bs[ldk + 2][nloc] = v.z; Bs[ldk + 3][nloc] = v.w;
        }
        __syncthreads();

#pragma unroll
        for (int k = 0; k < BK; k++) {
            float4 a0 = *reinterpret_cast<const float4*>(&As[k][ty * 4]);
            float4 a1 = *reinterpret_cast<const float4*>(&As[k][64 + ty * 4]);
            float4 b0 = *reinterpret_cast<const float4*>(&Bs[k][tx * 4]);
            float4 b1 = *reinterpret_cast<const float4*>(&Bs[k][64 + tx * 4]);
            unsigned long long bp[4];
            bp[0] = pk2(b0.x, b0.y); bp[1] = pk2(b0.z, b0.w);
            bp[2] = pk2(b1.x, b1.y); bp[3] = pk2(b1.z, b1.w);
            float av[8] = {a0.x, a0.y, a0.z, a0.w, a1.x, a1.y, a1.z, a1.w};
#pragma unroll
            for (int i = 0; i < 8; i++) {
                unsigned long long ad = pk2(av[i], av[i]);
#pragma unroll
                for (int j = 0; j < 4; j++) FMA2(acc[i][j], ad, bp[j]);
            }
        }
        __syncthreads();
    }

    // epilogue
#pragma unroll
    for (int i = 0; i < 8; i++) {
        int rloc = (i < 4) ? (ty * 4 + i) : (64 + ty * 4 + (i - 4));
        int row = row0 + rloc;
        if (row >= m_end) continue;
        float g = gate ? gate[row] : 1.0f;
        long long base = (long long)row * ldc;
#pragma unroll
        for (int j = 0; j < 4; j++) {
            float lo, hi;
            upk2(acc[i][j], lo, hi);
            int cl = (j < 2) ? (tx * 4 + j * 2) : (64 + tx * 4 + (j - 2) * 2);
            int c0 = col0 + cl;
            if (c0 + 1 < N) {
                float2 v = make_float2(lo * g, hi * g);
                *reinterpret_cast<float2*>(C + base + c0) = v;
            } else if (c0 < N) {
                C[base + c0] = lo * g;
            }
        }
    }
}

// ---------------- swiglu elementwise: bufA = silu(bufA) * bufB -------------
__global__ void swiglu_kernel(long long n4) {
    long long i = (long long)blockIdx.x * blockDim.x + threadIdx.x;
    if (i >= n4) return;
    float4 a = reinterpret_cast<float4*>(g_bufA)[i];
    float4 b = reinterpret_cast<float4*>(g_bufB)[i];
    a.x = a.x / (1.f + expf(-a.x)) * b.x;
    a.y = a.y / (1.f + expf(-a.y)) * b.y;
    a.z = a.z / (1.f + expf(-a.z)) * b.z;
    a.w = a.w / (1.f + expf(-a.w)) * b.w;
    reinterpret_cast<float4*>(g_bufA)[i] = a;
}

// ---------------- final deterministic add of the two routed slots ----------
__global__ void final_add_kernel(float* __restrict__ out) {
    int i = blockIdx.x * blockDim.x + threadIdx.x;   // over TT * (DD/4)
    if (i >= TT * (DD / 4)) return;
    int t = i >> 9;              // DD/4 = 512
    int c = i & 511;
    float4* o4 = reinterpret_cast<float4*>(out);
    const float4* y4 = reinterpret_cast<const float4*>(g_yslot);
    int p0 = g_tok_pos[2 * t], p1 = g_tok_pos[2 * t + 1];
    float4 v  = o4[(long long)t * 512 + c];
    float4 u0 = y4[(long long)p0 * 512 + c];
    float4 u1 = y4[(long long)p1 * 512 + c];
    v.x += u0.x + u1.x; v.y += u0.y + u1.y;
    v.z += u0.z + u1.z; v.w += u0.w + u1.w;
    o4[(long long)t * 512 + c] = v;
}

// ---------------- launch ----------------
extern "C" void kernel_launch(void* const* d_in, const int* in_sizes, int n_in,
                              void* d_out, int out_size) {
    const float* x   = (const float*)d_in[0];
    const float* rw  = (const float*)d_in[1];
    const float* w1  = (const float*)d_in[2];
    const float* w2  = (const float*)d_in[3];
    const float* w3  = (const float*)d_in[4];
    const float* sw1 = (const float*)d_in[5];
    const float* sw2 = (const float*)d_in[6];
    const float* sw3 = (const float*)d_in[7];
    float* out = (float*)d_out;

    float *pA = nullptr, *pB = nullptr, *pY = nullptr, *pGate = nullptr;
    int *pTok = nullptr, *pOff = nullptr;
    cudaGetSymbolAddress((void**)&pA,   g_bufA);
    cudaGetSymbolAddress((void**)&pB,   g_bufB);
    cudaGetSymbolAddress((void**)&pY,   g_yslot);
    cudaGetSymbolAddress((void**)&pTok, g_assign_tok);
    cudaGetSymbolAddress((void**)&pGate,g_assign_gate);
    cudaGetSymbolAddress((void**)&pOff, g_offsets);

    dim3 blk(256);

    // routing
    init_kernel<<<1, 32>>>();
    router_kernel<<<TT / 8, 256>>>(x, rw);
    scan_kernel<<<1, 32>>>(out + (long long)TT * DD);   // aux at end
    build_kernel<<<TT / 256, 256>>>();

    // ---- shared expert (dense over all tokens) ----
    dim3 g1s(TT / BM, (HH + BN - 1) / BN, 1);           // (64, 11, 1)
    gemm_nt<<<g1s, blk>>>(x, sw1, pA, nullptr, nullptr, nullptr,
                          TT, HH, DD, HH, 0);
    gemm_nt<<<g1s, blk>>>(x, sw3, pB, nullptr, nullptr, nullptr,
                          TT, HH, DD, HH, 0);
    {
        long long n4 = (long long)TT * HH / 4;
        swiglu_kernel<<<(unsigned)((n4 + 255) / 256), 256>>>(n4);
    }
    dim3 g2s(TT / BM, DD / BN, 1);                       // (64, 16, 1)
    gemm_nt<<<g2s, blk>>>(pA, sw2, out, nullptr, nullptr, nullptr,
                          TT, DD, HH, DD, 0);

    // ---- routed experts (grouped by segment) ----
    dim3 g1r(TT / BM, (HH + BN - 1) / BN, EE);           // (64, 11, 8)
    gemm_nt<<<g1r, blk>>>(x, w1, pA, pTok, nullptr, pOff,
                          TK, HH, DD, HH, (long long)HH * DD);
    gemm_nt<<<g1r, blk>>>(x, w3, pB, pTok, nullptr, pOff,
                          TK, HH, DD, HH, (long long)HH * DD);
    {
        long long n4 = (long long)TK * HH / 4;
        swiglu_kernel<<<(unsigned)((n4 + 255) / 256), 256>>>(n4);
    }
    dim3 g2r(TT / BM, DD / BN, EE);                      // (64, 16, 8)
    gemm_nt<<<g2r, blk>>>(pA, w2, pY, nullptr, pGate, pOff,
                          TK, DD, HH, DD, (long long)DD * HH);

    final_add_kernel<<<(TT * (DD / 4)) / 256, 256>>>(out);
}

// round 4
// speedup vs baseline: 2.1370x; 2.1370x over previous
#include <cuda_runtime.h>
#include <cuda_bf16.h>
#include <math.h>
#include <stdint.h>

// ---------------- problem constants ----------------
#define TT   8192              // tokens (B*S)
#define DD   2048              // model dim
#define HH   1368              // hidden dim
#define HP   1408              // hidden padded to 64
#define EE   8                 // experts
#define TK   16384             // T * K routed assignments
#define TKS  24576             // TK + TT (shared expert appended as segment 8)
#define WMAT (HH * DD)         // elements per weight matrix

// ---------------- static device scratch ----------------
__device__ __align__(16) float g_bufA[(size_t)TKS * HP];
__device__ __align__(16) float g_bufB[(size_t)TKS * HP];
__device__ __align__(16) float g_y[(size_t)TKS * DD];
__device__ __align__(16) __nv_bfloat16 g_xhi[(size_t)TKS * DD];
__device__ __align__(16) __nv_bfloat16 g_xlo[(size_t)TKS * DD];
__device__ __align__(16) __nv_bfloat16 g_hhi[(size_t)TKS * HP];
__device__ __align__(16) __nv_bfloat16 g_hlo[(size_t)TKS * HP];
__device__ __align__(16) __nv_bfloat16 g_w1h[(size_t)9 * WMAT];
__device__ __align__(16) __nv_bfloat16 g_w1l[(size_t)9 * WMAT];
__device__ __align__(16) __nv_bfloat16 g_w3h[(size_t)9 * WMAT];
__device__ __align__(16) __nv_bfloat16 g_w3l[(size_t)9 * WMAT];
__device__ __align__(16) __nv_bfloat16 g_w2h[(size_t)9 * WMAT];
__device__ __align__(16) __nv_bfloat16 g_w2l[(size_t)9 * WMAT];
__device__ int    g_tok[TKS];
__device__ float  g_gatev[TKS];
__device__ int    g_pos[2 * TT];
__device__ int2   g_top_e[TT];
__device__ float2 g_top_p[TT];
__device__ int    g_cnt1[EE];
__device__ int    g_cntA[EE];
__device__ int    g_cur[EE];
__device__ int    g_seg[10];
__device__ float  g_psum[EE];

// ---------------- PTX helpers (baseline-arch safe) ----------------
__device__ __forceinline__ unsigned smem_u32(const void* p) {
    unsigned a;
    asm("{ .reg .u64 t; cvta.to.shared.u64 t, %1; cvt.u32.u64 %0, t; }"
        : "=r"(a) : "l"(p));
    return a;
}
#define CP_COMMIT()  asm volatile("cp.async.commit_group;" ::: "memory")
#define CP_WAIT0()   asm volatile("cp.async.wait_group 0;" ::: "memory")
#define CP_WAIT1()   asm volatile("cp.async.wait_group 1;" ::: "memory")
#define CP16(dst, src, sz) \
    asm volatile("cp.async.cg.shared.global [%0], [%1], 16, %2;" \
                 :: "r"(dst), "l"(src), "r"(sz))

#define LDSM4(r, addr) \
    asm volatile("ldmatrix.sync.aligned.m8n8.x4.shared.b16 {%0,%1,%2,%3}, [%4];" \
        : "=r"((r)[0]), "=r"((r)[1]), "=r"((r)[2]), "=r"((r)[3]) : "r"(addr))

#define MMA16816(c, a, b0, b1) \
    asm volatile("mma.sync.aligned.m16n8k16.row.col.f32.bf16.bf16.f32 " \
        "{%0,%1,%2,%3}, {%4,%5,%6,%7}, {%8,%9}, {%0,%1,%2,%3};" \
        : "+f"((c)[0]), "+f"((c)[1]), "+f"((c)[2]), "+f"((c)[3]) \
        : "r"((a)[0]), "r"((a)[1]), "r"((a)[2]), "r"((a)[3]), "r"(b0), "r"(b1))

__device__ __forceinline__ void fsplit(float v, __nv_bfloat16& h, __nv_bfloat16& l) {
    h = __float2bfloat16_rn(v);
    l = __float2bfloat16_rn(v - __bfloat162float(h));
}

// ---------------- routing ----------------
__global__ void init_kernel() {
    int i = threadIdx.x;
    if (i < EE) { g_cnt1[i] = 0; g_cntA[i] = 0; g_psum[i] = 0.f; g_cur[i] = 0; }
}

__global__ void router_kernel(const float* __restrict__ x,
                              const float* __restrict__ rw) {
    __shared__ float s_psum[EE];
    __shared__ int s_cnt1[EE], s_cntA[EE];
    int tid = threadIdx.x;
    if (tid < EE) { s_psum[tid] = 0.f; s_cnt1[tid] = 0; s_cntA[tid] = 0; }
    __syncthreads();

    int warp = tid >> 5, lane = tid & 31;
    int t = blockIdx.x * 8 + warp;

    float acc[EE];
#pragma unroll
    for (int e = 0; e < EE; e++) acc[e] = 0.f;
    const float4* xr = reinterpret_cast<const float4*>(x + (long long)t * DD);
    for (int d4 = lane; d4 < DD / 4; d4 += 32) {
        float4 xv = xr[d4];
#pragma unroll
        for (int e = 0; e < EE; e++) {
            float4 wv = reinterpret_cast<const float4*>(rw + (long long)e * DD)[d4];
            acc[e] += xv.x * wv.x + xv.y * wv.y + xv.z * wv.z + xv.w * wv.w;
        }
    }
#pragma unroll
    for (int e = 0; e < EE; e++)
        for (int o = 16; o; o >>= 1)
            acc[e] += __shfl_xor_sync(0xffffffffu, acc[e], o);

    if (lane == 0) {
        float mx = acc[0];
#pragma unroll
        for (int e = 1; e < EE; e++) mx = fmaxf(mx, acc[e]);
        float p[EE], s = 0.f;
#pragma unroll
        for (int e = 0; e < EE; e++) { p[e] = expf(acc[e] - mx); s += p[e]; }
        float inv = 1.f / s;
        int e0 = 0;
#pragma unroll
        for (int e = 1; e < EE; e++) if (acc[e] > acc[e0]) e0 = e;
        int e1 = (e0 == 0) ? 1 : 0;
#pragma unroll
        for (int e = 0; e < EE; e++) if (e != e0 && acc[e] > acc[e1]) e1 = e;

        g_top_e[t] = make_int2(e0, e1);
        g_top_p[t] = make_float2(p[e0] * inv, p[e1] * inv);
        atomicAdd(&s_cnt1[e0], 1);
        atomicAdd(&s_cntA[e0], 1);
        atomicAdd(&s_cntA[e1], 1);
#pragma unroll
        for (int e = 0; e < EE; e++) atomicAdd(&s_psum[e], p[e] * inv);
    }
    __syncthreads();
    if (tid < EE) {
        atomicAdd(&g_psum[tid], s_psum[tid]);
        atomicAdd(&g_cnt1[tid], s_cnt1[tid]);
        atomicAdd(&g_cntA[tid], s_cntA[tid]);
    }
}

__global__ void scan_kernel(float* __restrict__ aux_out) {
    if (threadIdx.x == 0) {
        int off = 0;
        for (int e = 0; e < EE; e++) { g_seg[e] = off; off += g_cntA[e]; }
        g_seg[8] = TK;
        g_seg[9] = TKS;
        float aux = 0.f;
        const float invT = 1.0f / (float)TT;
        for (int e = 0; e < EE; e++)
            aux += ((float)g_cnt1[e] * invT) * (g_psum[e] * invT);
        aux_out[0] = 0.01f * (float)EE * aux;
    }
}

__global__ void build_kernel() {
    int t = blockIdx.x * blockDim.x + threadIdx.x;
    if (t >= TT) return;
    int2 e = g_top_e[t];
    float2 p = g_top_p[t];
    int pos0 = g_seg[e.x] + atomicAdd(&g_cur[e.x], 1);
    g_tok[pos0] = t; g_gatev[pos0] = p.x; g_pos[2 * t] = pos0;
    int pos1 = g_seg[e.y] + atomicAdd(&g_cur[e.y], 1);
    g_tok[pos1] = t; g_gatev[pos1] = p.y; g_pos[2 * t + 1] = pos1;
    g_tok[TK + t] = t; g_gatev[TK + t] = 1.0f;
}

// ---------------- gather + split x ----------------
__global__ void gather_split_x(const float* __restrict__ x) {
    int i = blockIdx.x * blockDim.x + threadIdx.x;
    if (i >= TKS * (DD / 4)) return;
    int s = i >> 9;
    int c = i & 511;
    int tok = g_tok[s];
    float4 v = reinterpret_cast<const float4*>(x)[(long long)tok * (DD / 4) + c];
    __nv_bfloat16 hx, lx, hy, ly, hz, lz, hw, lw;
    fsplit(v.x, hx, lx); fsplit(v.y, hy, ly);
    fsplit(v.z, hz, lz); fsplit(v.w, hw, lw);
    long long o = (long long)s * (DD / 2) + c * 2;
    reinterpret_cast<__nv_bfloat162*>(g_xhi)[o]     = __halves2bfloat162(hx, hy);
    reinterpret_cast<__nv_bfloat162*>(g_xhi)[o + 1] = __halves2bfloat162(hz, hw);
    reinterpret_cast<__nv_bfloat162*>(g_xlo)[o]     = __halves2bfloat162(lx, ly);
    reinterpret_cast<__nv_bfloat162*>(g_xlo)[o + 1] = __halves2bfloat162(lz, lw);
}

// ---------------- weight split ----------------
__global__ void split_w(const float* __restrict__ src,
                        __nv_bfloat16* __restrict__ hi,
                        __nv_bfloat16* __restrict__ lo, int n4) {
    int i = blockIdx.x * blockDim.x + threadIdx.x;
    if (i >= n4) return;
    float4 v = reinterpret_cast<const float4*>(src)[i];
    __nv_bfloat16 hx, lx, hy, ly, hz, lz, hw, lw;
    fsplit(v.x, hx, lx); fsplit(v.y, hy, ly);
    fsplit(v.z, hz, lz); fsplit(v.w, hw, lw);
    long long o = (long long)i * 2;
    reinterpret_cast<__nv_bfloat162*>(hi)[o]     = __halves2bfloat162(hx, hy);
    reinterpret_cast<__nv_bfloat162*>(hi)[o + 1] = __halves2bfloat162(hz, hw);
    reinterpret_cast<__nv_bfloat162*>(lo)[o]     = __halves2bfloat162(lx, ly);
    reinterpret_cast<__nv_bfloat162*>(lo)[o + 1] = __halves2bfloat162(lz, lw);
}

// ---------------- swiglu + split ----------------
__global__ void swiglu_split(int n4) {
    int i = blockIdx.x * blockDim.x + threadIdx.x;
    if (i >= n4) return;
    float4 a = reinterpret_cast<const float4*>(g_bufA)[i];
    float4 b = reinterpret_cast<const float4*>(g_bufB)[i];
    float4 h;
    h.x = a.x / (1.f + expf(-a.x)) * b.x;
    h.y = a.y / (1.f + expf(-a.y)) * b.y;
    h.z = a.z / (1.f + expf(-a.z)) * b.z;
    h.w = a.w / (1.f + expf(-a.w)) * b.w;
    __nv_bfloat16 hx, lx, hy, ly, hz, lz, hw, lw;
    fsplit(h.x, hx, lx); fsplit(h.y, hy, ly);
    fsplit(h.z, hz, lz); fsplit(h.w, hw, lw);
    long long o = (long long)i * 2;
    reinterpret_cast<__nv_bfloat162*>(g_hhi)[o]     = __halves2bfloat162(hx, hy);
    reinterpret_cast<__nv_bfloat162*>(g_hhi)[o + 1] = __halves2bfloat162(hz, hw);
    reinterpret_cast<__nv_bfloat162*>(g_hlo)[o]     = __halves2bfloat162(lx, ly);
    reinterpret_cast<__nv_bfloat162*>(g_hlo)[o + 1] = __halves2bfloat162(lz, lw);
}

// ============================================================================
// grouped split-bf16 GEMM via mma.sync m16n8k16 (baseline-arch tensor cores)
// C[m, col0:col0+128) = sum_k A[m,k] * W[z][n,k]
// A = Ah + Al, W = Wh + Wl; 3 products: Ah*Wh + Ah*Wl + Al*Wh (fp32 accum)
// 128x128 CTA tile, K32 chunks, 2-stage double buffer.
// ============================================================================
#define MPITCH 80                           // bytes per smem row (conflict-stagger)
#define MTILE  (128 * MPITCH)               // 10240 bytes per operand tile
#define MSTAGE (4 * MTILE)                  // 40960 bytes per stage (Ah,Al,Bh,Bl)
#define GSMEM  (2 * MSTAGE)                 // 81920 bytes total

__device__ __forceinline__ void ld_tiles(
    unsigned tb, int tid,
    const __nv_bfloat16* __restrict__ Ah, const __nv_bfloat16* __restrict__ Al,
    const __nv_bfloat16* __restrict__ Bh, const __nv_bfloat16* __restrict__ Bl,
    int row0, int lda, int col0, int nreal, int kreal, int kc0)
{
#pragma unroll
    for (int j = 0; j < 2; j++) {
        int idx = j * 256 + tid;         // 0..511
        int r = idx >> 2, c = idx & 3;   // tile row, 16B k-chunk
        unsigned off = (unsigned)(r * MPITCH + c * 16);
        long long ga = (long long)(row0 + r) * lda + kc0 + c * 8;
        CP16(tb + off,             Ah + ga, 16);
        CP16(tb + MTILE + off,     Al + ga, 16);
        int n = col0 + r, kg = kc0 + c * 8;
        int ok = (n < nreal && kg < kreal) ? 16 : 0;
        long long gb = ok ? ((long long)n * kreal + kg) : 0;
        CP16(tb + 2 * MTILE + off, Bh + gb, ok);
        CP16(tb + 3 * MTILE + off, Bl + gb, ok);
    }
    CP_COMMIT();
}

__global__ __launch_bounds__(256)
void gemm_sp(const __nv_bfloat16* __restrict__ Ah,
             const __nv_bfloat16* __restrict__ Al,
             const __nv_bfloat16* __restrict__ Wh,
             const __nv_bfloat16* __restrict__ Wl,
             float* __restrict__ C,
             const float* __restrict__ gate,
             int lda, int ldc, int nreal, int kreal, int kpad)
{
    extern __shared__ __align__(128) char smem[];
    int z  = blockIdx.z;
    int m0 = g_seg[z], m1 = g_seg[z + 1];
    int row0 = m0 + blockIdx.y * 128;
    if (row0 >= m1) return;
    int col0 = blockIdx.x * 128;

    const __nv_bfloat16* Bh = Wh + (long long)z * WMAT;
    const __nv_bfloat16* Bl = Wl + (long long)z * WMAT;

    unsigned sb = smem_u32(smem);
    int tid = threadIdx.x, wid = tid >> 5, lane = tid & 31;
    int nch = kpad / 32;
    int wm = wid & 3, wn = wid >> 2;          // warp -> (m32 slot, n64 slot)

    float acc[2][8][4];
#pragma unroll
    for (int t = 0; t < 2; t++)
#pragma unroll
        for (int n = 0; n < 8; n++)
#pragma unroll
            for (int q = 0; q < 4; q++) acc[t][n][q] = 0.f;

    // ldmatrix lane offsets (within a tile; k-step advance added later)
    unsigned a_off[2], b_off[4];
#pragma unroll
    for (int t = 0; t < 2; t++) {
        int rr = wm * 32 + t * 16 + ((lane >> 3) & 1) * 8 + (lane & 7);
        a_off[t] = (unsigned)(rr * MPITCH + (lane >> 4) * 16);
    }
#pragma unroll
    for (int p = 0; p < 4; p++) {
        int nn = wn * 64 + p * 16 + (lane >> 4) * 8 + (lane & 7);
        b_off[p] = (unsigned)(nn * MPITCH + ((lane >> 3) & 1) * 16);
    }

    // prologue: stage 0 <- chunk 0
    ld_tiles(sb, tid, Ah, Al, Bh, Bl, row0, lda, col0, nreal, kreal, 0);

    for (int i = 0; i < nch; i++) {
        if (i + 1 < nch) {
            ld_tiles(sb + ((i + 1) & 1) * MSTAGE, tid, Ah, Al, Bh, Bl,
                     row0, lda, col0, nreal, kreal, (i + 1) * 32);
            CP_WAIT1();                  // chunk i complete, chunk i+1 in flight
        } else {
            CP_WAIT0();                  // final chunk: everything complete
        }
        __syncthreads();

        unsigned tb = sb + (i & 1) * MSTAGE;
#pragma unroll
        for (int ks = 0; ks < 2; ks++) {
            unsigned kof = ks * 32;      // 16 bf16 = 32 bytes per k-step
            unsigned ah[2][4], al[2][4];
            LDSM4(ah[0], tb + a_off[0] + kof);
            LDSM4(ah[1], tb + a_off[1] + kof);
            LDSM4(al[0], tb + MTILE + a_off[0] + kof);
            LDSM4(al[1], tb + MTILE + a_off[1] + kof);
#pragma unroll
            for (int p = 0; p < 4; p++) {
                unsigned bh[4], bl[4];
                LDSM4(bh, tb + 2 * MTILE + b_off[p] + kof);
                LDSM4(bl, tb + 3 * MTILE + b_off[p] + kof);
#pragma unroll
                for (int t = 0; t < 2; t++) {
                    MMA16816(acc[t][2 * p],     ah[t], bh[0], bh[1]);
                    MMA16816(acc[t][2 * p],     ah[t], bl[0], bl[1]);
                    MMA16816(acc[t][2 * p],     al[t], bh[0], bh[1]);
                    MMA16816(acc[t][2 * p + 1], ah[t], bh[2], bh[3]);
                    MMA16816(acc[t][2 * p + 1], ah[t], bl[2], bl[3]);
                    MMA16816(acc[t][2 * p + 1], al[t], bh[2], bh[3]);
                }
            }
        }
        __syncthreads();                 // protect stage reuse next iteration
    }

    // epilogue
#pragma unroll
    for (int t = 0; t < 2; t++) {
        int r0 = row0 + wm * 32 + t * 16 + (lane >> 2);
        int r1 = r0 + 8;
        float g0 = 1.f, g1 = 1.f;
        bool a0 = (r0 < m1), a1 = (r1 < m1);
        if (gate != nullptr) {
            if (a0) g0 = gate[r0];
            if (a1) g1 = gate[r1];
        }
#pragma unroll
        for (int n = 0; n < 8; n++) {
            int cb = col0 + wn * 64 + n * 8 + 2 * (lane & 3);
            if (a0) {
                float2 v = make_float2(acc[t][n][0] * g0, acc[t][n][1] * g0);
                *reinterpret_cast<float2*>(C + (long long)r0 * ldc + cb) = v;
            }
            if (a1) {
                float2 v = make_float2(acc[t][n][2] * g1, acc[t][n][3] * g1);
                *reinterpret_cast<float2*>(C + (long long)r1 * ldc + cb) = v;
            }
        }
    }
}

// ---------------- final deterministic 3-slot add ----------------
__global__ void final_add(float* __restrict__ out) {
    int i = blockIdx.x * blockDim.x + threadIdx.x;
    if (i >= TT * (DD / 4)) return;
    int t = i >> 9, c = i & 511;
    int p0 = g_pos[2 * t], p1 = g_pos[2 * t + 1], p2 = TK + t;
    const float4* y4 = reinterpret_cast<const float4*>(g_y);
    float4 a = y4[(long long)p0 * 512 + c];
    float4 b = y4[(long long)p1 * 512 + c];
    float4 d = y4[(long long)p2 * 512 + c];
    float4 v;
    v.x = a.x + b.x + d.x; v.y = a.y + b.y + d.y;
    v.z = a.z + b.z + d.z; v.w = a.w + b.w + d.w;
    reinterpret_cast<float4*>(out)[(long long)t * 512 + c] = v;
}

// ---------------- launch ----------------
extern "C" void kernel_launch(void* const* d_in, const int* in_sizes, int n_in,
                              void* d_out, int out_size) {
    const float* x   = (const float*)d_in[0];
    const float* rw  = (const float*)d_in[1];
    const float* w1  = (const float*)d_in[2];
    const float* w2  = (const float*)d_in[3];
    const float* w3  = (const float*)d_in[4];
    const float* sw1 = (const float*)d_in[5];
    const float* sw2 = (const float*)d_in[6];
    const float* sw3 = (const float*)d_in[7];
    float* out = (float*)d_out;

    float *pBufA, *pBufB, *pY, *pGate;
    __nv_bfloat16 *pXh, *pXl, *pHh, *pHl;
    __nv_bfloat16 *pW1h, *pW1l, *pW3h, *pW3l, *pW2h, *pW2l;
    cudaGetSymbolAddress((void**)&pBufA, g_bufA);
    cudaGetSymbolAddress((void**)&pBufB, g_bufB);
    cudaGetSymbolAddress((void**)&pY,    g_y);
    cudaGetSymbolAddress((void**)&pGate, g_gatev);
    cudaGetSymbolAddress((void**)&pXh,   g_xhi);
    cudaGetSymbolAddress((void**)&pXl,   g_xlo);
    cudaGetSymbolAddress((void**)&pHh,   g_hhi);
    cudaGetSymbolAddress((void**)&pHl,   g_hlo);
    cudaGetSymbolAddress((void**)&pW1h,  g_w1h);
    cudaGetSymbolAddress((void**)&pW1l,  g_w1l);
    cudaGetSymbolAddress((void**)&pW3h,  g_w3h);
    cudaGetSymbolAddress((void**)&pW3l,  g_w3l);
    cudaGetSymbolAddress((void**)&pW2h,  g_w2h);
    cudaGetSymbolAddress((void**)&pW2l,  g_w2l);

    cudaFuncSetAttribute(gemm_sp, cudaFuncAttributeMaxDynamicSharedMemorySize, GSMEM);

    // routing
    init_kernel<<<1, 32>>>();
    router_kernel<<<TT / 8, 256>>>(x, rw);
    scan_kernel<<<1, 32>>>(out + (long long)TT * DD);
    build_kernel<<<TT / 256, 256>>>();

    // gather + splits
    gather_split_x<<<(TKS * (DD / 4) + 255) / 256, 256>>>(x);
    int nw = 8 * WMAT / 4, ns = WMAT / 4;
    split_w<<<(nw + 255) / 256, 256>>>(w1,  pW1h,            pW1l,            nw);
    split_w<<<(ns + 255) / 256, 256>>>(sw1, pW1h + (size_t)8 * WMAT, pW1l + (size_t)8 * WMAT, ns);
    split_w<<<(nw + 255) / 256, 256>>>(w3,  pW3h,            pW3l,            nw);
    split_w<<<(ns + 255) / 256, 256>>>(sw3, pW3h + (size_t)8 * WMAT, pW3l + (size_t)8 * WMAT, ns);
    split_w<<<(nw + 255) / 256, 256>>>(w2,  pW2h,            pW2l,            nw);
    split_w<<<(ns + 255) / 256, 256>>>(sw2, pW2h + (size_t)8 * WMAT, pW2l + (size_t)8 * WMAT, ns);

    // GEMM1: [TKS, DD] @ [HH, DD]^T -> bufA / bufB (ldc = HP)
    dim3 grid1(11, 128, 9);
    gemm_sp<<<grid1, 256, GSMEM>>>(pXh, pXl, pW1h, pW1l, pBufA, nullptr,
                                   DD, HP, HH, DD, DD);
    gemm_sp<<<grid1, 256, GSMEM>>>(pXh, pXl, pW3h, pW3l, pBufB, nullptr,
                                   DD, HP, HH, DD, DD);

    // swiglu + split to bf16
    {
        int n4 = TKS * HP / 4;
        swiglu_split<<<(n4 + 255) / 256, 256>>>(n4);
    }

    // GEMM2: [TKS, HP] @ [DD, HH]^T -> y (gated)
    dim3 grid2(16, 128, 9);
    gemm_sp<<<grid2, 256, GSMEM>>>(pHh, pHl, pW2h, pW2l, pY, pGate,
                                   HP, DD, DD, HH, HP);

    final_add<<<(TT * (DD / 4)) / 256, 256>>>(out);
}

// round 5
// speedup vs baseline: 2.1897x; 1.0247x over previous
#include <cuda_runtime.h>
#include <cuda_bf16.h>
#include <math.h>
#include <stdint.h>

// ---------------- problem constants ----------------
#define TT   8192              // tokens (B*S)
#define DD   2048              // model dim
#define HH   1368              // hidden dim
#define HP   1408              // hidden padded to 64
#define EE   8                 // experts
#define TK   16384             // T * K routed assignments
#define TKS  24576             // TK + TT (shared expert appended as segment 8)
#define WMAT (HH * DD)         // elements per weight matrix

// ---------------- static device scratch ----------------
__device__ __align__(16) float g_bufA[(size_t)TKS * HP];
__device__ __align__(16) float g_bufB[(size_t)TKS * HP];
__device__ __align__(16) float g_y[(size_t)TKS * DD];
__device__ __align__(16) __nv_bfloat16 g_xhi[(size_t)TKS * DD];
__device__ __align__(16) __nv_bfloat16 g_xlo[(size_t)TKS * DD];
__device__ __align__(16) __nv_bfloat16 g_hhi[(size_t)TKS * HP];
__device__ __align__(16) __nv_bfloat16 g_hlo[(size_t)TKS * HP];
__device__ __align__(16) __nv_bfloat16 g_w1h[(size_t)9 * WMAT];
__device__ __align__(16) __nv_bfloat16 g_w1l[(size_t)9 * WMAT];
__device__ __align__(16) __nv_bfloat16 g_w3h[(size_t)9 * WMAT];
__device__ __align__(16) __nv_bfloat16 g_w3l[(size_t)9 * WMAT];
__device__ __align__(16) __nv_bfloat16 g_w2h[(size_t)9 * WMAT];
__device__ __align__(16) __nv_bfloat16 g_w2l[(size_t)9 * WMAT];
__device__ int    g_tok[TKS];
__device__ float  g_gatev[TKS];
__device__ int    g_pos[2 * TT];
__device__ int2   g_top_e[TT];
__device__ float2 g_top_p[TT];
__device__ int    g_cnt1[EE];
__device__ int    g_cntA[EE];
__device__ int    g_cur[EE];
__device__ int    g_seg[10];
__device__ float  g_psum[EE];

// ---------------- PTX helpers (baseline-arch safe) ----------------
__device__ __forceinline__ unsigned smem_u32(const void* p) {
    unsigned a;
    asm("{ .reg .u64 t; cvta.to.shared.u64 t, %1; cvt.u32.u64 %0, t; }"
        : "=r"(a) : "l"(p));
    return a;
}
#define CP_COMMIT()  asm volatile("cp.async.commit_group;" ::: "memory")
#define CP_WAIT0()   asm volatile("cp.async.wait_group 0;" ::: "memory")
#define CP_WAIT1()   asm volatile("cp.async.wait_group 1;" ::: "memory")
#define CP16(dst, src, sz) \
    asm volatile("cp.async.cg.shared.global [%0], [%1], 16, %2;" \
                 :: "r"(dst), "l"(src), "r"(sz))

#define LDSM4(r, addr) \
    asm volatile("ldmatrix.sync.aligned.m8n8.x4.shared.b16 {%0,%1,%2,%3}, [%4];" \
        : "=r"((r)[0]), "=r"((r)[1]), "=r"((r)[2]), "=r"((r)[3]) : "r"(addr))

#define MMA16816(c, a, b0, b1) \
    asm volatile("mma.sync.aligned.m16n8k16.row.col.f32.bf16.bf16.f32 " \
        "{%0,%1,%2,%3}, {%4,%5,%6,%7}, {%8,%9}, {%0,%1,%2,%3};" \
        : "+f"((c)[0]), "+f"((c)[1]), "+f"((c)[2]), "+f"((c)[3]) \
        : "r"((a)[0]), "r"((a)[1]), "r"((a)[2]), "r"((a)[3]), "r"(b0), "r"(b1))

__device__ __forceinline__ void fsplit(float v, __nv_bfloat16& h, __nv_bfloat16& l) {
    h = __float2bfloat16_rn(v);
    l = __float2bfloat16_rn(v - __bfloat162float(h));
}

// ---------------- routing ----------------
__global__ void init_kernel() {
    int i = threadIdx.x;
    if (i < EE) { g_cnt1[i] = 0; g_cntA[i] = 0; g_psum[i] = 0.f; g_cur[i] = 0; }
}

__global__ void router_kernel(const float* __restrict__ x,
                              const float* __restrict__ rw) {
    __shared__ float s_psum[EE];
    __shared__ int s_cnt1[EE], s_cntA[EE];
    int tid = threadIdx.x;
    if (tid < EE) { s_psum[tid] = 0.f; s_cnt1[tid] = 0; s_cntA[tid] = 0; }
    __syncthreads();

    int warp = tid >> 5, lane = tid & 31;
    int t = blockIdx.x * 8 + warp;

    float acc[EE];
#pragma unroll
    for (int e = 0; e < EE; e++) acc[e] = 0.f;
    const float4* xr = reinterpret_cast<const float4*>(x + (long long)t * DD);
    for (int d4 = lane; d4 < DD / 4; d4 += 32) {
        float4 xv = xr[d4];
#pragma unroll
        for (int e = 0; e < EE; e++) {
            float4 wv = reinterpret_cast<const float4*>(rw + (long long)e * DD)[d4];
            acc[e] += xv.x * wv.x + xv.y * wv.y + xv.z * wv.z + xv.w * wv.w;
        }
    }
#pragma unroll
    for (int e = 0; e < EE; e++)
        for (int o = 16; o; o >>= 1)
            acc[e] += __shfl_xor_sync(0xffffffffu, acc[e], o);

    if (lane == 0) {
        float mx = acc[0];
#pragma unroll
        for (int e = 1; e < EE; e++) mx = fmaxf(mx, acc[e]);
        float p[EE], s = 0.f;
#pragma unroll
        for (int e = 0; e < EE; e++) { p[e] = expf(acc[e] - mx); s += p[e]; }
        float inv = 1.f / s;
        int e0 = 0;
#pragma unroll
        for (int e = 1; e < EE; e++) if (acc[e] > acc[e0]) e0 = e;
        int e1 = (e0 == 0) ? 1 : 0;
#pragma unroll
        for (int e = 0; e < EE; e++) if (e != e0 && acc[e] > acc[e1]) e1 = e;

        g_top_e[t] = make_int2(e0, e1);
        g_top_p[t] = make_float2(p[e0] * inv, p[e1] * inv);
        atomicAdd(&s_cnt1[e0], 1);
        atomicAdd(&s_cntA[e0], 1);
        atomicAdd(&s_cntA[e1], 1);
#pragma unroll
        for (int e = 0; e < EE; e++) atomicAdd(&s_psum[e], p[e] * inv);
    }
    __syncthreads();
    if (tid < EE) {
        atomicAdd(&g_psum[tid], s_psum[tid]);
        atomicAdd(&g_cnt1[tid], s_cnt1[tid]);
        atomicAdd(&g_cntA[tid], s_cntA[tid]);
    }
}

__global__ void scan_kernel(float* __restrict__ aux_out) {
    if (threadIdx.x == 0) {
        int off = 0;
        for (int e = 0; e < EE; e++) { g_seg[e] = off; off += g_cntA[e]; }
        g_seg[8] = TK;
        g_seg[9] = TKS;
        float aux = 0.f;
        const float invT = 1.0f / (float)TT;
        for (int e = 0; e < EE; e++)
            aux += ((float)g_cnt1[e] * invT) * (g_psum[e] * invT);
        aux_out[0] = 0.01f * (float)EE * aux;
    }
}

__global__ void build_kernel() {
    int t = blockIdx.x * blockDim.x + threadIdx.x;
    if (t >= TT) return;
    int2 e = g_top_e[t];
    float2 p = g_top_p[t];
    int pos0 = g_seg[e.x] + atomicAdd(&g_cur[e.x], 1);
    g_tok[pos0] = t; g_gatev[pos0] = p.x; g_pos[2 * t] = pos0;
    int pos1 = g_seg[e.y] + atomicAdd(&g_cur[e.y], 1);
    g_tok[pos1] = t; g_gatev[pos1] = p.y; g_pos[2 * t + 1] = pos1;
    g_tok[TK + t] = t; g_gatev[TK + t] = 1.0f;
}

// ---------------- gather + split x ----------------
__global__ void gather_split_x(const float* __restrict__ x) {
    int i = blockIdx.x * blockDim.x + threadIdx.x;
    if (i >= TKS * (DD / 4)) return;
    int s = i >> 9;
    int c = i & 511;
    int tok = g_tok[s];
    float4 v = reinterpret_cast<const float4*>(x)[(long long)tok * (DD / 4) + c];
    __nv_bfloat16 hx, lx, hy, ly, hz, lz, hw, lw;
    fsplit(v.x, hx, lx); fsplit(v.y, hy, ly);
    fsplit(v.z, hz, lz); fsplit(v.w, hw, lw);
    long long o = (long long)s * (DD / 2) + c * 2;
    reinterpret_cast<__nv_bfloat162*>(g_xhi)[o]     = __halves2bfloat162(hx, hy);
    reinterpret_cast<__nv_bfloat162*>(g_xhi)[o + 1] = __halves2bfloat162(hz, hw);
    reinterpret_cast<__nv_bfloat162*>(g_xlo)[o]     = __halves2bfloat162(lx, ly);
    reinterpret_cast<__nv_bfloat162*>(g_xlo)[o + 1] = __halves2bfloat162(lz, lw);
}

// ---------------- weight split ----------------
__global__ void split_w(const float* __restrict__ src,
                        __nv_bfloat16* __restrict__ hi,
                        __nv_bfloat16* __restrict__ lo, int n4) {
    int i = blockIdx.x * blockDim.x + threadIdx.x;
    if (i >= n4) return;
    float4 v = reinterpret_cast<const float4*>(src)[i];
    __nv_bfloat16 hx, lx, hy, ly, hz, lz, hw, lw;
    fsplit(v.x, hx, lx); fsplit(v.y, hy, ly);
    fsplit(v.z, hz, lz); fsplit(v.w, hw, lw);
    long long o = (long long)i * 2;
    reinterpret_cast<__nv_bfloat162*>(hi)[o]     = __halves2bfloat162(hx, hy);
    reinterpret_cast<__nv_bfloat162*>(hi)[o + 1] = __halves2bfloat162(hz, hw);
    reinterpret_cast<__nv_bfloat162*>(lo)[o]     = __halves2bfloat162(lx, ly);
    reinterpret_cast<__nv_bfloat162*>(lo)[o + 1] = __halves2bfloat162(lz, lw);
}

// ---------------- swiglu + split ----------------
__global__ void swiglu_split(int n4) {
    int i = blockIdx.x * blockDim.x + threadIdx.x;
    if (i >= n4) return;
    float4 a = reinterpret_cast<const float4*>(g_bufA)[i];
    float4 b = reinterpret_cast<const float4*>(g_bufB)[i];
    float4 h;
    h.x = a.x / (1.f + __expf(-a.x)) * b.x;
    h.y = a.y / (1.f + __expf(-a.y)) * b.y;
    h.z = a.z / (1.f + __expf(-a.z)) * b.z;
    h.w = a.w / (1.f + __expf(-a.w)) * b.w;
    __nv_bfloat16 hx, lx, hy, ly, hz, lz, hw, lw;
    fsplit(h.x, hx, lx); fsplit(h.y, hy, ly);
    fsplit(h.z, hz, lz); fsplit(h.w, hw, lw);
    long long o = (long long)i * 2;
    reinterpret_cast<__nv_bfloat162*>(g_hhi)[o]     = __halves2bfloat162(hx, hy);
    reinterpret_cast<__nv_bfloat162*>(g_hhi)[o + 1] = __halves2bfloat162(hz, hw);
    reinterpret_cast<__nv_bfloat162*>(g_hlo)[o]     = __halves2bfloat162(lx, ly);
    reinterpret_cast<__nv_bfloat162*>(g_hlo)[o + 1] = __halves2bfloat162(lz, lw);
}

// ============================================================================
// grouped split-bf16 GEMM via mma.sync m16n8k16
// C[m, col0:col0+128) = sum_k A[m,k] * W[z][n,k]
// A = Ah + Al, W = Wh + Wl; 3 products: Ah*Wh + Ah*Wl + Al*Wh (fp32 accum)
// 128x128 CTA tile, K32 chunks, 2-stage double buffer.
// MMAs grouped by split-term so each accumulator's reuse distance is 16.
// ============================================================================
#define MPITCH 80                           // bytes per smem row (conflict-stagger)
#define MTILE  (128 * MPITCH)               // 10240 bytes per operand tile
#define MSTAGE (4 * MTILE)                  // 40960 bytes per stage (Ah,Al,Bh,Bl)
#define GSMEM  (2 * MSTAGE)                 // 81920 bytes total

__device__ __forceinline__ void ld_tiles(
    unsigned tb, int tid,
    const __nv_bfloat16* __restrict__ Ah, const __nv_bfloat16* __restrict__ Al,
    const __nv_bfloat16* __restrict__ Bh, const __nv_bfloat16* __restrict__ Bl,
    int row0, int lda, int col0, int nreal, int kreal, int kc0)
{
#pragma unroll
    for (int j = 0; j < 2; j++) {
        int idx = j * 256 + tid;         // 0..511
        int r = idx >> 2, c = idx & 3;   // tile row, 16B k-chunk
        unsigned off = (unsigned)(r * MPITCH + c * 16);
        long long ga = (long long)(row0 + r) * lda + kc0 + c * 8;
        CP16(tb + off,             Ah + ga, 16);
        CP16(tb + MTILE + off,     Al + ga, 16);
        int n = col0 + r, kg = kc0 + c * 8;
        int ok = (n < nreal && kg < kreal) ? 16 : 0;
        long long gb = ok ? ((long long)n * kreal + kg) : 0;
        CP16(tb + 2 * MTILE + off, Bh + gb, ok);
        CP16(tb + 3 * MTILE + off, Bl + gb, ok);
    }
    CP_COMMIT();
}

__global__ __launch_bounds__(256)
void gemm_sp(const __nv_bfloat16* __restrict__ Ah,
             const __nv_bfloat16* __restrict__ Al,
             const __nv_bfloat16* __restrict__ Wh,
             const __nv_bfloat16* __restrict__ Wl,
             float* __restrict__ C,
             const float* __restrict__ gate,
             int lda, int ldc, int nreal, int kreal, int kpad)
{
    extern __shared__ __align__(128) char smem[];
    int z  = blockIdx.z;
    int m0 = g_seg[z], m1 = g_seg[z + 1];
    int row0 = m0 + blockIdx.y * 128;
    if (row0 >= m1) return;
    int col0 = blockIdx.x * 128;

    const __nv_bfloat16* Bh = Wh + (long long)z * WMAT;
    const __nv_bfloat16* Bl = Wl + (long long)z * WMAT;

    unsigned sb = smem_u32(smem);
    int tid = threadIdx.x, wid = tid >> 5, lane = tid & 31;
    int nch = kpad / 32;
    int wm = wid & 3, wn = wid >> 2;          // warp -> (m32 slot, n64 slot)

    float acc[2][8][4];
#pragma unroll
    for (int t = 0; t < 2; t++)
#pragma unroll
        for (int n = 0; n < 8; n++)
#pragma unroll
            for (int q = 0; q < 4; q++) acc[t][n][q] = 0.f;

    // ldmatrix lane offsets (within a tile; k-step advance added later)
    unsigned a_off[2], b_off[4];
#pragma unroll
    for (int t = 0; t < 2; t++) {
        int rr = wm * 32 + t * 16 + ((lane >> 3) & 1) * 8 + (lane & 7);
        a_off[t] = (unsigned)(rr * MPITCH + (lane >> 4) * 16);
    }
#pragma unroll
    for (int p = 0; p < 4; p++) {
        int nn = wn * 64 + p * 16 + (lane >> 4) * 8 + (lane & 7);
        b_off[p] = (unsigned)(nn * MPITCH + ((lane >> 3) & 1) * 16);
    }

    // prologue: stage 0 <- chunk 0
    ld_tiles(sb, tid, Ah, Al, Bh, Bl, row0, lda, col0, nreal, kreal, 0);

    for (int i = 0; i < nch; i++) {
        if (i + 1 < nch) {
            ld_tiles(sb + ((i + 1) & 1) * MSTAGE, tid, Ah, Al, Bh, Bl,
                     row0, lda, col0, nreal, kreal, (i + 1) * 32);
            CP_WAIT1();                  // chunk i complete, chunk i+1 in flight
        } else {
            CP_WAIT0();                  // final chunk: everything complete
        }
        __syncthreads();

        unsigned tb = sb + (i & 1) * MSTAGE;
#pragma unroll
        for (int ks = 0; ks < 2; ks++) {
            unsigned kof = ks * 32;      // 16 bf16 = 32 bytes per k-step
            unsigned ah[2][4], al[2][4], bhv[4][4], blv[4][4];
            LDSM4(ah[0], tb + a_off[0] + kof);
            LDSM4(ah[1], tb + a_off[1] + kof);
            LDSM4(al[0], tb + MTILE + a_off[0] + kof);
            LDSM4(al[1], tb + MTILE + a_off[1] + kof);
#pragma unroll
            for (int p = 0; p < 4; p++) {
                LDSM4(bhv[p], tb + 2 * MTILE + b_off[p] + kof);
                LDSM4(blv[p], tb + 3 * MTILE + b_off[p] + kof);
            }
            // term 1: Ah * Bh  (16 independent MMAs)
#pragma unroll
            for (int p = 0; p < 4; p++)
#pragma unroll
                for (int t = 0; t < 2; t++) {
                    MMA16816(acc[t][2 * p],     ah[t], bhv[p][0], bhv[p][1]);
                    MMA16816(acc[t][2 * p + 1], ah[t], bhv[p][2], bhv[p][3]);
                }
            // term 2: Ah * Bl
#pragma unroll
            for (int p = 0; p < 4; p++)
#pragma unroll
                for (int t = 0; t < 2; t++) {
                    MMA16816(acc[t][2 * p],     ah[t], blv[p][0], blv[p][1]);
                    MMA16816(acc[t][2 * p + 1], ah[t], blv[p][2], blv[p][3]);
                }
            // term 3: Al * Bh
#pragma unroll
            for (int p = 0; p < 4; p++)
#pragma unroll
                for (int t = 0; t < 2; t++) {
                    MMA16816(acc[t][2 * p],     al[t], bhv[p][0], bhv[p][1]);
                    MMA16816(acc[t][2 * p + 1], al[t], bhv[p][2], bhv[p][3]);
                }
        }
        __syncthreads();                 // protect stage reuse next iteration
    }

    // epilogue
#pragma unroll
    for (int t = 0; t < 2; t++) {
        int r0 = row0 + wm * 32 + t * 16 + (lane >> 2);
        int r1 = r0 + 8;
        float g0 = 1.f, g1 = 1.f;
        bool a0 = (r0 < m1), a1 = (r1 < m1);
        if (gate != nullptr) {
            if (a0) g0 = gate[r0];
            if (a1) g1 = gate[r1];
        }
#pragma unroll
        for (int n = 0; n < 8; n++) {
            int cb = col0 + wn * 64 + n * 8 + 2 * (lane & 3);
            if (a0) {
                float2 v = make_float2(acc[t][n][0] * g0, acc[t][n][1] * g0);
                *reinterpret_cast<float2*>(C + (long long)r0 * ldc + cb) = v;
            }
            if (a1) {
                float2 v = make_float2(acc[t][n][2] * g1, acc[t][n][3] * g1);
                *reinterpret_cast<float2*>(C + (long long)r1 * ldc + cb) = v;
            }
        }
    }
}

// ---------------- final deterministic 3-slot add ----------------
__global__ void final_add(float* __restrict__ out) {
    int i = blockIdx.x * blockDim.x + threadIdx.x;
    if (i >= TT * (DD / 4)) return;
    int t = i >> 9, c = i & 511;
    int p0 = g_pos[2 * t], p1 = g_pos[2 * t + 1], p2 = TK + t;
    const float4* y4 = reinterpret_cast<const float4*>(g_y);
    float4 a = y4[(long long)p0 * 512 + c];
    float4 b = y4[(long long)p1 * 512 + c];
    float4 d = y4[(long long)p2 * 512 + c];
    float4 v;
    v.x = a.x + b.x + d.x; v.y = a.y + b.y + d.y;
    v.z = a.z + b.z + d.z; v.w = a.w + b.w + d.w;
    reinterpret_cast<float4*>(out)[(long long)t * 512 + c] = v;
}

// ---------------- launch ----------------
extern "C" void kernel_launch(void* const* d_in, const int* in_sizes, int n_in,
                              void* d_out, int out_size) {
    const float* x   = (const float*)d_in[0];
    const float* rw  = (const float*)d_in[1];
    const float* w1  = (const float*)d_in[2];
    const float* w2  = (const float*)d_in[3];
    const float* w3  = (const float*)d_in[4];
    const float* sw1 = (const float*)d_in[5];
    const float* sw2 = (const float*)d_in[6];
    const float* sw3 = (const float*)d_in[7];
    float* out = (float*)d_out;

    float *pBufA, *pBufB, *pY, *pGate;
    __nv_bfloat16 *pXh, *pXl, *pHh, *pHl;
    __nv_bfloat16 *pW1h, *pW1l, *pW3h, *pW3l, *pW2h, *pW2l;
    cudaGetSymbolAddress((void**)&pBufA, g_bufA);
    cudaGetSymbolAddress((void**)&pBufB, g_bufB);
    cudaGetSymbolAddress((void**)&pY,    g_y);
    cudaGetSymbolAddress((void**)&pGate, g_gatev);
    cudaGetSymbolAddress((void**)&pXh,   g_xhi);
    cudaGetSymbolAddress((void**)&pXl,   g_xlo);
    cudaGetSymbolAddress((void**)&pHh,   g_hhi);
    cudaGetSymbolAddress((void**)&pHl,   g_hlo);
    cudaGetSymbolAddress((void**)&pW1h,  g_w1h);
    cudaGetSymbolAddress((void**)&pW1l,  g_w1l);
    cudaGetSymbolAddress((void**)&pW3h,  g_w3h);
    cudaGetSymbolAddress((void**)&pW3l,  g_w3l);
    cudaGetSymbolAddress((void**)&pW2h,  g_w2h);
    cudaGetSymbolAddress((void**)&pW2l,  g_w2l);

    cudaFuncSetAttribute(gemm_sp, cudaFuncAttributeMaxDynamicSharedMemorySize, GSMEM);

    // routing
    init_kernel<<<1, 32>>>();
    router_kernel<<<TT / 8, 256>>>(x, rw);
    scan_kernel<<<1, 32>>>(out + (long long)TT * DD);
    build_kernel<<<TT / 256, 256>>>();

    // gather + splits
    gather_split_x<<<(TKS * (DD / 4) + 255) / 256, 256>>>(x);
    int nw = 8 * WMAT / 4, ns = WMAT / 4;
    split_w<<<(nw + 255) / 256, 256>>>(w1,  pW1h,            pW1l,            nw);
    split_w<<<(ns + 255) / 256, 256>>>(sw1, pW1h + (size_t)8 * WMAT, pW1l + (size_t)8 * WMAT, ns);
    split_w<<<(nw + 255) / 256, 256>>>(w3,  pW3h,            pW3l,            nw);
    split_w<<<(ns + 255) / 256, 256>>>(sw3, pW3h + (size_t)8 * WMAT, pW3l + (size_t)8 * WMAT, ns);
    split_w<<<(nw + 255) / 256, 256>>>(w2,  pW2h,            pW2l,            nw);
    split_w<<<(ns + 255) / 256, 256>>>(sw2, pW2h + (size_t)8 * WMAT, pW2l + (size_t)8 * WMAT, ns);

    // GEMM1: [TKS, DD] @ [HH, DD]^T -> bufA / bufB (ldc = HP)
    dim3 grid1(11, 128, 9);
    gemm_sp<<<grid1, 256, GSMEM>>>(pXh, pXl, pW1h, pW1l, pBufA, nullptr,
                                   DD, HP, HH, DD, DD);
    gemm_sp<<<grid1, 256, GSMEM>>>(pXh, pXl, pW3h, pW3l, pBufB, nullptr,
                                   DD, HP, HH, DD, DD);

    // swiglu + split to bf16
    {
        int n4 = TKS * HP / 4;
        swiglu_split<<<(n4 + 255) / 256, 256>>>(n4);
    }

    // GEMM2: [TKS, HP] @ [DD, HH]^T -> y (gated)
    dim3 grid2(16, 128, 9);
    gemm_sp<<<grid2, 256, GSMEM>>>(pHh, pHl, pW2h, pW2l, pY, pGate,
                                   HP, DD, DD, HH, HP);

    final_add<<<(TT * (DD / 4)) / 256, 256>>>(out);
}